// round 2
// baseline (speedup 1.0000x reference)
#include <cuda_runtime.h>
#include <math.h>

// ---------------- problem constants ----------------
#define D_    512
#define H_    8
#define L_    6
#define FF_   2048
#define S_    512
#define B_    32
#define IN_   64
#define HD_   64
#define MROWS (B_ * S_)          // 16384 token rows
#define NBH   (B_ * H_)          // 256 attention batches

// ---------------- scratch (device globals; no allocation allowed) ----------------
__device__ float g_x   [MROWS * D_];               // activations (B,S,D)
__device__ float g_big [MROWS * FF_];              // qkv (uses 16384*1536) / ff hidden
__device__ float g_sc  [(long long)NBH * S_ * S_]; // attention scores (256,512,512)
__device__ float g_att [MROWS * D_];               // proj outputs
__device__ float g_m   [MROWS * D_];               // merged attention output
__device__ float g_h   [B_ * FF_];                 // head hidden

// ---------------- tiled SGEMM: C = alpha*(A@op(B) + bias), optional relu ----------------
// MODE 0: generic batched (A += z*sA etc.)
// MODE 1: attention scores  A=Q,B=K read from qkv (B,S,3D); C = scores + z*S*S
// MODE 2: attention P@V     A=scores; B=V from qkv; C written into merged (B,S,D)
// BT=true : B is (N,K) row-major (NT form, x @ W.T)
// BT=false: B is (K,N) row-major (NN form, P @ V)
#define BM 128
#define BN 128
#define BK 8

template<int MODE, bool BT, bool BIAS, bool RELU>
__global__ __launch_bounds__(256)
void sgemm(const float* __restrict__ A, const float* __restrict__ B,
           const float* __restrict__ bias, float* __restrict__ C,
           int M, int N, int K, int lda, int ldb, int ldc,
           long long sA, long long sB, long long sC, float alpha)
{
    __shared__ float As[BK][BM];
    __shared__ float Bs[BK][BN];

    const int z = blockIdx.z;
    if (MODE == 0) {
        A += z * sA;  B += z * sB;  C += z * sC;
    } else if (MODE == 1) {
        const long long boff = (long long)(z >> 3) * S_ * 3 * D_ + (z & 7) * HD_;
        A += boff;                 // Q rows, lda = 3*D
        B += boff + D_;            // K rows, ldb = 3*D
        C += (long long)z * S_ * S_;
    } else { // MODE == 2
        A += (long long)z * S_ * S_;                                    // scores
        B += (long long)(z >> 3) * S_ * 3 * D_ + (z & 7) * HD_ + 2 * D_; // V, ldb=3*D
        C += (long long)(z >> 3) * S_ * D_ + (z & 7) * HD_;              // merged out, ldc=D
    }

    const int m0 = blockIdx.y * BM;
    const int n0 = blockIdx.x * BN;
    const int tid = threadIdx.x;

    // A-tile load mapping: 128 rows x 8 cols, 2 threads per row (float4 each)
    const int arow = tid >> 1;
    const int acol = (tid & 1) * 4;
    // NN B-tile mapping: 8 rows x 128 cols
    const int bkrow = tid >> 5;
    const int bncol = (tid & 31) * 4;

    const int tx = tid & 15;      // n-dir
    const int ty = tid >> 4;      // m-dir

    float acc[8][8];
#pragma unroll
    for (int i = 0; i < 8; i++)
#pragma unroll
        for (int j = 0; j < 8; j++) acc[i][j] = 0.f;

    for (int k0 = 0; k0 < K; k0 += BK) {
        // load A tile (guard rows vs M)
        float4 av = make_float4(0.f, 0.f, 0.f, 0.f);
        if (m0 + arow < M)
            av = *(const float4*)&A[(long long)(m0 + arow) * lda + k0 + acol];
        As[acol + 0][arow] = av.x;
        As[acol + 1][arow] = av.y;
        As[acol + 2][arow] = av.z;
        As[acol + 3][arow] = av.w;

        if (BT) {
            float4 bv = make_float4(0.f, 0.f, 0.f, 0.f);
            if (n0 + arow < N)
                bv = *(const float4*)&B[(long long)(n0 + arow) * ldb + k0 + acol];
            Bs[acol + 0][arow] = bv.x;
            Bs[acol + 1][arow] = bv.y;
            Bs[acol + 2][arow] = bv.z;
            Bs[acol + 3][arow] = bv.w;
        } else {
            float4 bv = make_float4(0.f, 0.f, 0.f, 0.f);
            if (n0 + bncol < N)
                bv = *(const float4*)&B[(long long)(k0 + bkrow) * ldb + n0 + bncol];
            *(float4*)&Bs[bkrow][bncol] = bv;
        }
        __syncthreads();

#pragma unroll
        for (int kk = 0; kk < BK; kk++) {
            float a[8], b[8];
            *(float4*)&a[0] = *(const float4*)&As[kk][ty * 8];
            *(float4*)&a[4] = *(const float4*)&As[kk][ty * 8 + 4];
            *(float4*)&b[0] = *(const float4*)&Bs[kk][tx * 8];
            *(float4*)&b[4] = *(const float4*)&Bs[kk][tx * 8 + 4];
#pragma unroll
            for (int i = 0; i < 8; i++)
#pragma unroll
                for (int j = 0; j < 8; j++)
                    acc[i][j] += a[i] * b[j];
        }
        __syncthreads();
    }

#pragma unroll
    for (int i = 0; i < 8; i++) {
        int row = m0 + ty * 8 + i;
        if (row >= M) continue;
#pragma unroll
        for (int j = 0; j < 8; j++) {
            int col = n0 + tx * 8 + j;
            if (col >= N) continue;
            float v = acc[i][j];
            if (BIAS) v += bias[col];
            v *= alpha;
            if (RELU) v = fmaxf(v, 0.f);
            C[(long long)row * ldc + col] = v;
        }
    }
}

// ---------------- positional encoding add ----------------
__global__ void add_pe(float* __restrict__ x)
{
    int idx = blockIdx.x * blockDim.x + threadIdx.x;
    if (idx >= MROWS * D_) return;
    int d = idx & (D_ - 1);
    int s = (idx >> 9) & (S_ - 1);
    int j2 = d & ~1;                                    // even index 2j
    float ang = (float)s * expf((float)j2 * (-9.210340371976184f / (float)D_));
    x[idx] += (d & 1) ? cosf(ang) : sinf(ang);
}

// ---------------- row softmax, 512 cols, scale folded in ----------------
__global__ __launch_bounds__(128)
void softmax512(float* __restrict__ sc)
{
    long long row = blockIdx.x;
    float* p = sc + row * S_;
    int t = threadIdx.x;                                // 128 threads * 4
    const float scale = 0.125f;                         // 1/sqrt(64)

    float4 v = ((float4*)p)[t];
    v.x *= scale; v.y *= scale; v.z *= scale; v.w *= scale;

    float mx = fmaxf(fmaxf(v.x, v.y), fmaxf(v.z, v.w));
#pragma unroll
    for (int off = 16; off > 0; off >>= 1)
        mx = fmaxf(mx, __shfl_xor_sync(0xffffffffu, mx, off));
    __shared__ float sm[4];
    if ((t & 31) == 0) sm[t >> 5] = mx;
    __syncthreads();
    mx = fmaxf(fmaxf(sm[0], sm[1]), fmaxf(sm[2], sm[3]));

    v.x = expf(v.x - mx); v.y = expf(v.y - mx);
    v.z = expf(v.z - mx); v.w = expf(v.w - mx);
    float s = v.x + v.y + v.z + v.w;
#pragma unroll
    for (int off = 16; off > 0; off >>= 1)
        s += __shfl_xor_sync(0xffffffffu, s, off);
    __syncthreads();
    if ((t & 31) == 0) sm[t >> 5] = s;
    __syncthreads();
    s = sm[0] + sm[1] + sm[2] + sm[3];
    float inv = 1.f / s;
    v.x *= inv; v.y *= inv; v.z *= inv; v.w *= inv;
    ((float4*)p)[t] = v;
}

// ---------------- y = LayerNorm(x + r) * g + b ----------------
__global__ __launch_bounds__(128)
void add_ln(const float* __restrict__ x, const float* __restrict__ r,
            const float* __restrict__ g, const float* __restrict__ b,
            float* __restrict__ y)
{
    long long row = blockIdx.x;
    int t = threadIdx.x;                                // 128 threads * 4
    float4 a = ((const float4*)(x + row * D_))[t];
    float4 c = ((const float4*)(r + row * D_))[t];
    a.x += c.x; a.y += c.y; a.z += c.z; a.w += c.w;

    float sum = a.x + a.y + a.z + a.w;
    float sq  = a.x * a.x + a.y * a.y + a.z * a.z + a.w * a.w;
#pragma unroll
    for (int off = 16; off > 0; off >>= 1) {
        sum += __shfl_xor_sync(0xffffffffu, sum, off);
        sq  += __shfl_xor_sync(0xffffffffu, sq,  off);
    }
    __shared__ float s1[4], s2[4];
    if ((t & 31) == 0) { s1[t >> 5] = sum; s2[t >> 5] = sq; }
    __syncthreads();
    sum = s1[0] + s1[1] + s1[2] + s1[3];
    sq  = s2[0] + s2[1] + s2[2] + s2[3];

    float mean = sum * (1.f / D_);
    float var  = sq * (1.f / D_) - mean * mean;
    float inv  = rsqrtf(var + 1e-5f);

    float4 gg = ((const float4*)g)[t];
    float4 bb = ((const float4*)b)[t];
    float4 o;
    o.x = (a.x - mean) * inv * gg.x + bb.x;
    o.y = (a.y - mean) * inv * gg.y + bb.y;
    o.z = (a.z - mean) * inv * gg.z + bb.z;
    o.w = (a.w - mean) * inv * gg.w + bb.w;
    ((float4*)(y + row * D_))[t] = o;
}

// ---------------- final head: out[m] = dot(h[m], w2) + b2 ----------------
__global__ __launch_bounds__(256)
void head_out(const float* __restrict__ h, const float* __restrict__ w2,
              const float* __restrict__ b2, float* __restrict__ out)
{
    int m = blockIdx.x;
    int t = threadIdx.x;
    float s = 0.f;
    for (int k = t; k < FF_; k += 256)
        s += h[m * FF_ + k] * w2[k];
#pragma unroll
    for (int off = 16; off > 0; off >>= 1)
        s += __shfl_xor_sync(0xffffffffu, s, off);
    __shared__ float sm[8];
    if ((t & 31) == 0) sm[t >> 5] = s;
    __syncthreads();
    if (t == 0) {
        float tot = 0.f;
#pragma unroll
        for (int w = 0; w < 8; w++) tot += sm[w];
        out[m] = tot + b2[0];
    }
}

// ---------------- orchestration ----------------
extern "C" void kernel_launch(void* const* d_in, const int* in_sizes, int n_in,
                              void* d_out, int out_size)
{
    const float* src       = (const float*)d_in[0];
    const float* inp_w     = (const float*)d_in[1];
    const float* inp_b     = (const float*)d_in[2];
    const float* in_proj_w = (const float*)d_in[3];
    const float* in_proj_b = (const float*)d_in[4];
    const float* out_w     = (const float*)d_in[5];
    const float* out_b     = (const float*)d_in[6];
    const float* ff_w1     = (const float*)d_in[7];
    const float* ff_b1     = (const float*)d_in[8];
    const float* ff_w2     = (const float*)d_in[9];
    const float* ff_b2     = (const float*)d_in[10];
    const float* ln1_g     = (const float*)d_in[11];
    const float* ln1_b     = (const float*)d_in[12];
    const float* ln2_g     = (const float*)d_in[13];
    const float* ln2_b     = (const float*)d_in[14];
    const float* op_w1     = (const float*)d_in[15];
    const float* op_b1     = (const float*)d_in[16];
    const float* op_w2     = (const float*)d_in[17];
    const float* op_b2     = (const float*)d_in[18];
    float* out = (float*)d_out;

    float *x, *big, *sc, *att, *mg, *hh;
    cudaGetSymbolAddress((void**)&x,   g_x);
    cudaGetSymbolAddress((void**)&big, g_big);
    cudaGetSymbolAddress((void**)&sc,  g_sc);
    cudaGetSymbolAddress((void**)&att, g_att);
    cudaGetSymbolAddress((void**)&mg,  g_m);
    cudaGetSymbolAddress((void**)&hh,  g_h);

    const int ELT = (MROWS * D_) / 256;

    // input projection: x = (src @ inp_w.T + inp_b) * sqrt(D)
    sgemm<0, true, true, false><<<dim3(4, 128, 1), 256>>>(
        src, inp_w, inp_b, x, MROWS, D_, IN_, IN_, IN_, D_, 0, 0, 0,
        22.62741699796952f /* sqrt(512) */);
    add_pe<<<ELT, 256>>>(x);

    for (int i = 0; i < L_; i++) {
        // qkv = x @ in_proj_w[i].T + in_proj_b[i]   -> big (B,S,3D)
        sgemm<0, true, true, false><<<dim3(12, 128, 1), 256>>>(
            x, in_proj_w + (long long)i * 3 * D_ * D_, in_proj_b + i * 3 * D_,
            big, MROWS, 3 * D_, D_, D_, D_, 3 * D_, 0, 0, 0, 1.f);

        // scores[b,h] = Q @ K^T, operands read straight from qkv layout
        sgemm<1, true, false, false><<<dim3(4, 4, NBH), 256>>>(
            big, big, nullptr, sc,
            S_, S_, HD_, 3 * D_, 3 * D_, S_, 0, 0, 0, 1.f);
        softmax512<<<NBH * S_, 128>>>(sc);

        // O[b,h] = P @ V, written directly into merged (B,S,D) layout
        sgemm<2, false, false, false><<<dim3(1, 4, NBH), 256>>>(
            sc, big, nullptr, mg,
            S_, HD_, S_, S_, 3 * D_, D_, 0, 0, 0, 1.f);

        // attention out-proj
        sgemm<0, true, true, false><<<dim3(4, 128, 1), 256>>>(
            mg, out_w + (long long)i * D_ * D_, out_b + i * D_,
            att, MROWS, D_, D_, D_, D_, D_, 0, 0, 0, 1.f);
        add_ln<<<MROWS, 128>>>(x, att, ln1_g + i * D_, ln1_b + i * D_, x);

        // FFN
        sgemm<0, true, true, true><<<dim3(16, 128, 1), 256>>>(
            x, ff_w1 + (long long)i * FF_ * D_, ff_b1 + i * FF_,
            big, MROWS, FF_, D_, D_, D_, FF_, 0, 0, 0, 1.f);
        sgemm<0, true, true, false><<<dim3(4, 128, 1), 256>>>(
            big, ff_w2 + (long long)i * D_ * FF_, ff_b2 + i * D_,
            att, MROWS, D_, FF_, FF_, FF_, D_, 0, 0, 0, 1.f);
        add_ln<<<MROWS, 128>>>(x, att, ln2_g + i * D_, ln2_b + i * D_, x);
    }

    // head: last token rows via lda = S*D (row stride jumps one batch element)
    sgemm<0, true, true, true><<<dim3(16, 1, 1), 256>>>(
        x + (S_ - 1) * D_, op_w1, op_b1, hh,
        B_, FF_, D_, S_ * D_, D_, FF_, 0, 0, 0, 1.f);
    head_out<<<B_, 256>>>(hh, op_w2, op_b2, out);
}

// round 4
// speedup vs baseline: 2.8068x; 2.8068x over previous
#include <cuda_runtime.h>
#include <cuda_bf16.h>
#include <cstdint>
#include <math.h>

// ---------------- problem constants ----------------
#define D_    512
#define H_    8
#define L_    6
#define FF_   2048
#define S_    512
#define B_    32
#define IN_   64
#define HD_   64
#define MROWS (B_ * S_)          // 16384 token rows
#define NBH   (B_ * H_)          // 256 attention batches

// ---------------- scratch (device globals; no allocation allowed) ----------------
__device__ __align__(256) float g_x   [MROWS * D_];               // activations (B,S,D)
__device__ __align__(256) float g_big [MROWS * FF_];              // qkv (B,S,3D) / ff hidden
__device__ __align__(256) float g_sc  [(long long)NBH * S_ * S_]; // attention scores
__device__ __align__(256) float g_att [MROWS * D_];               // proj outputs
__device__ __align__(256) float g_m   [MROWS * D_];               // merged attention output
__device__ __align__(256) float g_vt  [NBH * HD_ * S_];           // V^T per (b,h): (HD,S)
__device__ __align__(256) float g_h   [B_ * FF_];                 // head hidden

// ============================================================================
// helpers
// ============================================================================
__device__ __forceinline__ uint32_t smem_u32(const void* p) {
    uint32_t a;
    asm("{ .reg .u64 t; cvta.to.shared.u64 t, %1; cvt.u32.u64 %0, t; }"
        : "=r"(a) : "l"(p));
    return a;
}

__device__ __forceinline__ void ldm4(uint32_t r[4], uint32_t addr) {
    asm volatile("ldmatrix.sync.aligned.m8n8.x4.shared.b16 {%0,%1,%2,%3}, [%4];"
                 : "=r"(r[0]), "=r"(r[1]), "=r"(r[2]), "=r"(r[3]) : "r"(addr));
}

__device__ __forceinline__ void mma_bf16(float c[4], const uint32_t a[4],
                                         const uint32_t b[2]) {
    asm volatile(
        "mma.sync.aligned.m16n8k16.row.col.f32.bf16.bf16.f32 "
        "{%0,%1,%2,%3}, {%4,%5,%6,%7}, {%8,%9}, {%0,%1,%2,%3};"
        : "+f"(c[0]), "+f"(c[1]), "+f"(c[2]), "+f"(c[3])
        : "r"(a[0]), "r"(a[1]), "r"(a[2]), "r"(a[3]), "r"(b[0]), "r"(b[1]));
}

// fp32 -> (bf16 hi, bf16 lo) convert + store 4 k-elems (8B each) at padded offset
__device__ __forceinline__ void cvt_st_pad(char* hi_p, char* lo_p, int off, float4 v) {
    __nv_bfloat162 h0 = __floats2bfloat162_rn(v.x, v.y);
    __nv_bfloat162 h1 = __floats2bfloat162_rn(v.z, v.w);
    float2 f0 = __bfloat1622float2(h0);
    float2 f1 = __bfloat1622float2(h1);
    __nv_bfloat162 l0 = __floats2bfloat162_rn(v.x - f0.x, v.y - f0.y);
    __nv_bfloat162 l1 = __floats2bfloat162_rn(v.z - f1.x, v.w - f1.y);
    uint2 hu, lu;
    hu.x = *(uint32_t*)&h0; hu.y = *(uint32_t*)&h1;
    lu.x = *(uint32_t*)&l0; lu.y = *(uint32_t*)&l1;
    *(uint2*)(hi_p + off) = hu;
    *(uint2*)(lo_p + off) = lu;
}

// 80-byte row stride: 32 bf16 of data (64B) + 16B pad -> conflict-free ldmatrix
#define RSTR 80
#define ASZ  (128 * RSTR)

// Stage 128x32 A tile and BNx32 B tile: fp32 gmem -> bf16 hi/lo smem
template<int BN>
__device__ __forceinline__ void stage_pad(
    const float* __restrict__ A, const float* __restrict__ B,
    char* buf, int m0, int n0, int k0, int lda, int ldb, int tid)
{
    char* Ah = buf;            char* Al = buf + ASZ;
    char* Bh = buf + 2 * ASZ;  char* Bl = Bh + BN * RSTR;
#pragma unroll
    for (int it = 0; it < 4; it++) {
        int idx = tid + it * 256;
        int r = idx >> 3, c4 = idx & 7;
        float4 v = *(const float4*)&A[(long long)(m0 + r) * lda + k0 + c4 * 4];
        cvt_st_pad(Ah, Al, r * RSTR + c4 * 8, v);
    }
#pragma unroll
    for (int it = 0; it < BN / 32; it++) {
        int idx = tid + it * 256;
        int r = idx >> 3, c4 = idx & 7;
        float4 v = *(const float4*)&B[(long long)(n0 + r) * ldb + k0 + c4 * 4];
        cvt_st_pad(Bh, Bl, r * RSTR + c4 * 8, v);
    }
}

// ============================================================================
// bf16x3 mma.sync GEMM: C = alpha*(A @ B^T + bias), optional relu.
// A (M,K) row-major, B (N,K) row-major. CTA tile 128 x BN x 32, 8 warps.
// MODE 0: generic; MODE 1: scores from qkv layout; MODE 2: P@V, merged C.
// ============================================================================
template<int MODE, int BN, bool BIAS, bool RELU>
__global__ void __launch_bounds__(256) mmagemm(
    const float* __restrict__ A, const float* __restrict__ B,
    const float* __restrict__ bias, float* __restrict__ C,
    int K, int lda, int ldb, int ldc,
    long long sA, long long sB, long long sC, float alpha)
{
    constexpr int NWN = BN / 32;          // warps along N
    constexpr int NWM = 8 / NWN;          // warps along M
    constexpr int WM  = 128 / NWM;        // rows per warp
    constexpr int NMA = WM / 16;          // m16 atoms per warp
    constexpr int NNA = 4;                // n8 atoms per warp (32/8)
    constexpr int BSZ = BN * RSTR;
    constexpr int STAGE = 2 * ASZ + 2 * BSZ;

    extern __shared__ char sm[];
    const int tid = threadIdx.x, lane = tid & 31, wid = tid >> 5;

    const int z = blockIdx.z;
    if (MODE == 0) { A += z * sA; B += z * sB; C += z * sC; }
    else if (MODE == 1) {
        long long off = (long long)(z >> 3) * S_ * 3 * D_ + (z & 7) * HD_;
        A += off;  B += off + D_;  C += (long long)z * S_ * S_;
    } else {
        A += (long long)z * S_ * S_;
        B += (long long)z * HD_ * S_;
        C += (long long)(z >> 3) * S_ * D_ + (z & 7) * HD_;
    }

    const int m0 = blockIdx.y * 128;
    const int n0 = blockIdx.x * BN;
    const int wmb = (wid / NWN) * WM;
    const int wnb = (wid % NWN) * 32;

    const uint32_t sb = smem_u32(sm);

    float acc[NMA][NNA][4];
#pragma unroll
    for (int i = 0; i < NMA; i++)
#pragma unroll
        for (int j = 0; j < NNA; j++)
#pragma unroll
            for (int q = 0; q < 4; q++) acc[i][j][q] = 0.f;

    const int NKB = K >> 5;
    stage_pad<BN>(A, B, sm, m0, n0, 0, lda, ldb, tid);
    __syncthreads();

    for (int kb = 0; kb < NKB; kb++) {
        const int cur = kb & 1;
        const uint32_t aH = sb + cur * STAGE;
        const uint32_t aL = aH + ASZ;
        const uint32_t bH = aH + 2 * ASZ;
        const uint32_t bL = bH + BSZ;

        const int lr = lane & 15, lh = lane >> 4;
        const int r8 = lane & 7, sel = (lane >> 3) & 1, hb = (lane >> 4) & 1;

#pragma unroll
        for (int kk = 0; kk < 32; kk += 16) {
            uint32_t ah[NMA][4], al[NMA][4], bh[NNA][2], bl[NNA][2];
#pragma unroll
            for (int ma = 0; ma < NMA; ma++) {
                uint32_t row = wmb + ma * 16 + lr;
                uint32_t cb  = (kk + lh * 8) * 2;
                ldm4(ah[ma], aH + row * RSTR + cb);
                ldm4(al[ma], aL + row * RSTR + cb);
            }
#pragma unroll
            for (int nb = 0; nb < NNA / 2; nb++) {
                uint32_t row = wnb + nb * 16 + hb * 8 + r8;
                uint32_t cb  = (kk + sel * 8) * 2;
                uint32_t t[4];
                ldm4(t, bH + row * RSTR + cb);
                bh[2 * nb][0] = t[0]; bh[2 * nb][1] = t[1];
                bh[2 * nb + 1][0] = t[2]; bh[2 * nb + 1][1] = t[3];
                ldm4(t, bL + row * RSTR + cb);
                bl[2 * nb][0] = t[0]; bl[2 * nb][1] = t[1];
                bl[2 * nb + 1][0] = t[2]; bl[2 * nb + 1][1] = t[3];
            }
#pragma unroll
            for (int ma = 0; ma < NMA; ma++)
#pragma unroll
                for (int na = 0; na < NNA; na++)
                    mma_bf16(acc[ma][na], ah[ma], bh[na]);
#pragma unroll
            for (int ma = 0; ma < NMA; ma++)
#pragma unroll
                for (int na = 0; na < NNA; na++)
                    mma_bf16(acc[ma][na], ah[ma], bl[na]);
#pragma unroll
            for (int ma = 0; ma < NMA; ma++)
#pragma unroll
                for (int na = 0; na < NNA; na++)
                    mma_bf16(acc[ma][na], al[ma], bh[na]);
        }

        if (kb + 1 < NKB)
            stage_pad<BN>(A, B, sm + (cur ^ 1) * STAGE, m0, n0, (kb + 1) << 5,
                          lda, ldb, tid);
        __syncthreads();
    }

    // epilogue: d-frag (row = lane>>2 [+8], col = (lane&3)*2 [+1])
#pragma unroll
    for (int ma = 0; ma < NMA; ma++) {
#pragma unroll
        for (int na = 0; na < NNA; na++) {
            int r = m0 + wmb + ma * 16 + (lane >> 2);
            int c = n0 + wnb + na * 8 + (lane & 3) * 2;
            float b0 = 0.f, b1 = 0.f;
            if (BIAS) { b0 = __ldg(&bias[c]); b1 = __ldg(&bias[c + 1]); }
#pragma unroll
            for (int half = 0; half < 2; half++) {
                int rr = r + half * 8;
                float v0 = (acc[ma][na][2 * half]     + b0) * alpha;
                float v1 = (acc[ma][na][2 * half + 1] + b1) * alpha;
                if (RELU) { v0 = fmaxf(v0, 0.f); v1 = fmaxf(v1, 0.f); }
                C[(long long)rr * ldc + c]     = v0;
                C[(long long)rr * ldc + c + 1] = v1;
            }
        }
    }
}

// ============================================================================
// V^T per (b,h): vt[z][hd][s] = qkv[b][s][2D + h*64 + hd]
// ============================================================================
__global__ void transposeV(const float* __restrict__ qkv, float* __restrict__ vt)
{
    __shared__ float t[32][33];
    int z = blockIdx.z;
    int s0 = blockIdx.x * 32, d0 = blockIdx.y * 32;
    int b = z >> 3, h = z & 7;
    const float* src = qkv + (long long)b * S_ * 3 * D_ + 2 * D_ + h * HD_;
    int tx = threadIdx.x, ty = threadIdx.y;
#pragma unroll
    for (int r = 0; r < 4; r++) {
        int s = s0 + ty + r * 8;
        t[ty + r * 8][tx] = src[(long long)s * (3 * D_) + d0 + tx];
    }
    __syncthreads();
    float* dst = vt + (long long)z * HD_ * S_;
#pragma unroll
    for (int r = 0; r < 4; r++) {
        int d = d0 + ty + r * 8;
        dst[(long long)d * S_ + s0 + tx] = t[tx][ty + r * 8];
    }
}

// ---------------- positional encoding add ----------------
__global__ void add_pe(float* __restrict__ x)
{
    int idx = blockIdx.x * blockDim.x + threadIdx.x;
    if (idx >= MROWS * D_) return;
    int d = idx & (D_ - 1);
    int s = (idx >> 9) & (S_ - 1);
    int j2 = d & ~1;
    float ang = (float)s * expf((float)j2 * (-9.210340371976184f / (float)D_));
    x[idx] += (d & 1) ? cosf(ang) : sinf(ang);
}

// ---------------- row softmax, 512 cols, scale folded in ----------------
__global__ __launch_bounds__(128)
void softmax512(float* __restrict__ sc)
{
    long long row = blockIdx.x;
    float* p = sc + row * S_;
    int t = threadIdx.x;
    const float scale = 0.125f;

    float4 v = ((float4*)p)[t];
    v.x *= scale; v.y *= scale; v.z *= scale; v.w *= scale;

    float mx = fmaxf(fmaxf(v.x, v.y), fmaxf(v.z, v.w));
#pragma unroll
    for (int off = 16; off > 0; off >>= 1)
        mx = fmaxf(mx, __shfl_xor_sync(0xffffffffu, mx, off));
    __shared__ float sm[4];
    if ((t & 31) == 0) sm[t >> 5] = mx;
    __syncthreads();
    mx = fmaxf(fmaxf(sm[0], sm[1]), fmaxf(sm[2], sm[3]));

    v.x = expf(v.x - mx); v.y = expf(v.y - mx);
    v.z = expf(v.z - mx); v.w = expf(v.w - mx);
    float s = v.x + v.y + v.z + v.w;
#pragma unroll
    for (int off = 16; off > 0; off >>= 1)
        s += __shfl_xor_sync(0xffffffffu, s, off);
    __syncthreads();
    if ((t & 31) == 0) sm[t >> 5] = s;
    __syncthreads();
    s = sm[0] + sm[1] + sm[2] + sm[3];
    float inv = 1.f / s;
    v.x *= inv; v.y *= inv; v.z *= inv; v.w *= inv;
    ((float4*)p)[t] = v;
}

// ---------------- y = LayerNorm(x + r) * g + b ----------------
__global__ __launch_bounds__(128)
void add_ln(const float* __restrict__ x, const float* __restrict__ r,
            const float* __restrict__ g, const float* __restrict__ b,
            float* __restrict__ y)
{
    long long row = blockIdx.x;
    int t = threadIdx.x;
    float4 a = ((const float4*)(x + row * D_))[t];
    float4 c = ((const float4*)(r + row * D_))[t];
    a.x += c.x; a.y += c.y; a.z += c.z; a.w += c.w;

    float sum = a.x + a.y + a.z + a.w;
    float sq  = a.x * a.x + a.y * a.y + a.z * a.z + a.w * a.w;
#pragma unroll
    for (int off = 16; off > 0; off >>= 1) {
        sum += __shfl_xor_sync(0xffffffffu, sum, off);
        sq  += __shfl_xor_sync(0xffffffffu, sq,  off);
    }
    __shared__ float s1[4], s2[4];
    if ((t & 31) == 0) { s1[t >> 5] = sum; s2[t >> 5] = sq; }
    __syncthreads();
    sum = s1[0] + s1[1] + s1[2] + s1[3];
    sq  = s2[0] + s2[1] + s2[2] + s2[3];

    float mean = sum * (1.f / D_);
    float var  = sq * (1.f / D_) - mean * mean;
    float inv  = rsqrtf(var + 1e-5f);

    float4 gg = ((const float4*)g)[t];
    float4 bb = ((const float4*)b)[t];
    float4 o;
    o.x = (a.x - mean) * inv * gg.x + bb.x;
    o.y = (a.y - mean) * inv * gg.y + bb.y;
    o.z = (a.z - mean) * inv * gg.z + bb.z;
    o.w = (a.w - mean) * inv * gg.w + bb.w;
    ((float4*)(y + row * D_))[t] = o;
}

// ---------------- small fp32 SGEMM for the head (M=32) ----------------
#define BMH 128
#define BNH 128
#define BKH 8
template<bool BIAS, bool RELU>
__global__ __launch_bounds__(256)
void sgemm32(const float* __restrict__ A, const float* __restrict__ B,
             const float* __restrict__ bias, float* __restrict__ C,
             int M, int N, int K, int lda, int ldb, int ldc)
{
    __shared__ float As[BKH][BMH];
    __shared__ float Bs[BKH][BNH];
    const int m0 = blockIdx.y * BMH;
    const int n0 = blockIdx.x * BNH;
    const int tid = threadIdx.x;
    const int arow = tid >> 1;
    const int acol = (tid & 1) * 4;
    const int tx = tid & 15;
    const int ty = tid >> 4;

    float acc[8][8];
#pragma unroll
    for (int i = 0; i < 8; i++)
#pragma unroll
        for (int j = 0; j < 8; j++) acc[i][j] = 0.f;

    for (int k0 = 0; k0 < K; k0 += BKH) {
        float4 av = make_float4(0.f, 0.f, 0.f, 0.f);
        if (m0 + arow < M)
            av = *(const float4*)&A[(long long)(m0 + arow) * lda + k0 + acol];
        As[acol + 0][arow] = av.x; As[acol + 1][arow] = av.y;
        As[acol + 2][arow] = av.z; As[acol + 3][arow] = av.w;
        float4 bv = make_float4(0.f, 0.f, 0.f, 0.f);
        if (n0 + arow < N)
            bv = *(const float4*)&B[(long long)(n0 + arow) * ldb + k0 + acol];
        Bs[acol + 0][arow] = bv.x; Bs[acol + 1][arow] = bv.y;
        Bs[acol + 2][arow] = bv.z; Bs[acol + 3][arow] = bv.w;
        __syncthreads();
#pragma unroll
        for (int kk = 0; kk < BKH; kk++) {
            float a[8], b[8];
            *(float4*)&a[0] = *(const float4*)&As[kk][ty * 8];
            *(float4*)&a[4] = *(const float4*)&As[kk][ty * 8 + 4];
            *(float4*)&b[0] = *(const float4*)&Bs[kk][tx * 8];
            *(float4*)&b[4] = *(const float4*)&Bs[kk][tx * 8 + 4];
#pragma unroll
            for (int i = 0; i < 8; i++)
#pragma unroll
                for (int j = 0; j < 8; j++)
                    acc[i][j] += a[i] * b[j];
        }
        __syncthreads();
    }
#pragma unroll
    for (int i = 0; i < 8; i++) {
        int row = m0 + ty * 8 + i;
        if (row >= M) continue;
#pragma unroll
        for (int j = 0; j < 8; j++) {
            int col = n0 + tx * 8 + j;
            if (col >= N) continue;
            float v = acc[i][j];
            if (BIAS) v += bias[col];
            if (RELU) v = fmaxf(v, 0.f);
            C[(long long)row * ldc + col] = v;
        }
    }
}

// ---------------- final head: out[m] = dot(h[m], w2) + b2 ----------------
__global__ __launch_bounds__(256)
void head_out(const float* __restrict__ h, const float* __restrict__ w2,
              const float* __restrict__ b2, float* __restrict__ out)
{
    int m = blockIdx.x;
    int t = threadIdx.x;
    float s = 0.f;
    for (int k = t; k < FF_; k += 256)
        s += h[m * FF_ + k] * w2[k];
#pragma unroll
    for (int off = 16; off > 0; off >>= 1)
        s += __shfl_xor_sync(0xffffffffu, s, off);
    __shared__ float sm[8];
    if ((t & 31) == 0) sm[t >> 5] = s;
    __syncthreads();
    if (t == 0) {
        float tot = 0.f;
#pragma unroll
        for (int w = 0; w < 8; w++) tot += sm[w];
        out[m] = tot + b2[0];
    }
}

// ---------------- orchestration ----------------
static constexpr int STAGE128 = 2 * 128 * RSTR + 2 * 128 * RSTR;  // 40960
static constexpr int STAGE64  = 2 * 128 * RSTR + 2 * 64 * RSTR;   // 30720
static constexpr int SMEM_128 = 2 * STAGE128;                      // 81920
static constexpr int SMEM_64  = 2 * STAGE64;                       // 61440

extern "C" void kernel_launch(void* const* d_in, const int* in_sizes, int n_in,
                              void* d_out, int out_size)
{
    const float* src       = (const float*)d_in[0];
    const float* inp_w     = (const float*)d_in[1];
    const float* inp_b     = (const float*)d_in[2];
    const float* in_proj_w = (const float*)d_in[3];
    const float* in_proj_b = (const float*)d_in[4];
    const float* out_w     = (const float*)d_in[5];
    const float* out_b     = (const float*)d_in[6];
    const float* ff_w1     = (const float*)d_in[7];
    const float* ff_b1     = (const float*)d_in[8];
    const float* ff_w2     = (const float*)d_in[9];
    const float* ff_b2     = (const float*)d_in[10];
    const float* ln1_g     = (const float*)d_in[11];
    const float* ln1_b     = (const float*)d_in[12];
    const float* ln2_g     = (const float*)d_in[13];
    const float* ln2_b     = (const float*)d_in[14];
    const float* op_w1     = (const float*)d_in[15];
    const float* op_b1     = (const float*)d_in[16];
    const float* op_w2     = (const float*)d_in[17];
    const float* op_b2     = (const float*)d_in[18];
    float* out = (float*)d_out;

    float *x, *big, *sc, *att, *mg, *vt, *hh;
    cudaGetSymbolAddress((void**)&x,   g_x);
    cudaGetSymbolAddress((void**)&big, g_big);
    cudaGetSymbolAddress((void**)&sc,  g_sc);
    cudaGetSymbolAddress((void**)&att, g_att);
    cudaGetSymbolAddress((void**)&mg,  g_m);
    cudaGetSymbolAddress((void**)&vt,  g_vt);
    cudaGetSymbolAddress((void**)&hh,  g_h);

    cudaFuncSetAttribute(mmagemm<0, 128, true,  false>, cudaFuncAttributeMaxDynamicSharedMemorySize, SMEM_128);
    cudaFuncSetAttribute(mmagemm<0, 128, true,  true >, cudaFuncAttributeMaxDynamicSharedMemorySize, SMEM_128);
    cudaFuncSetAttribute(mmagemm<1, 128, false, false>, cudaFuncAttributeMaxDynamicSharedMemorySize, SMEM_128);
    cudaFuncSetAttribute(mmagemm<2, 64,  false, false>, cudaFuncAttributeMaxDynamicSharedMemorySize, SMEM_64);

    const int ELT = (MROWS * D_) / 256;

    // input projection: x = (src @ inp_w.T + inp_b) * sqrt(D)
    mmagemm<0, 128, true, false><<<dim3(4, 128, 1), 256, SMEM_128>>>(
        src, inp_w, inp_b, x, IN_, IN_, IN_, D_, 0, 0, 0, 22.62741699796952f);
    add_pe<<<ELT, 256>>>(x);

    for (int i = 0; i < L_; i++) {
        // qkv = x @ in_proj_w[i].T + in_proj_b[i]   -> big (B,S,3D)
        mmagemm<0, 128, true, false><<<dim3(12, 128, 1), 256, SMEM_128>>>(
            x, in_proj_w + (long long)i * 3 * D_ * D_, in_proj_b + i * 3 * D_,
            big, D_, D_, D_, 3 * D_, 0, 0, 0, 1.f);

        transposeV<<<dim3(16, 2, NBH), dim3(32, 8)>>>(big, vt);

        // scores[b,h] = Q @ K^T (operand bases from qkv layout)
        mmagemm<1, 128, false, false><<<dim3(4, 4, NBH), 256, SMEM_128>>>(
            big, big, nullptr, sc, HD_, 3 * D_, 3 * D_, S_, 0, 0, 0, 1.f);
        softmax512<<<NBH * S_, 128>>>(sc);

        // O[b,h] = P @ V (V^T buffer), written directly into merged (B,S,D)
        mmagemm<2, 64, false, false><<<dim3(1, 4, NBH), 256, SMEM_64>>>(
            sc, vt, nullptr, mg, S_, S_, S_, D_, 0, 0, 0, 1.f);

        // attention out-proj
        mmagemm<0, 128, true, false><<<dim3(4, 128, 1), 256, SMEM_128>>>(
            mg, out_w + (long long)i * D_ * D_, out_b + i * D_,
            att, D_, D_, D_, D_, 0, 0, 0, 1.f);
        add_ln<<<MROWS, 128>>>(x, att, ln1_g + i * D_, ln1_b + i * D_, x);

        // FFN
        mmagemm<0, 128, true, true><<<dim3(16, 128, 1), 256, SMEM_128>>>(
            x, ff_w1 + (long long)i * FF_ * D_, ff_b1 + i * FF_,
            big, D_, D_, D_, FF_, 0, 0, 0, 1.f);
        mmagemm<0, 128, true, false><<<dim3(4, 128, 1), 256, SMEM_128>>>(
            big, ff_w2 + (long long)i * D_ * FF_, ff_b2 + i * D_,
            att, FF_, FF_, FF_, D_, 0, 0, 0, 1.f);
        add_ln<<<MROWS, 128>>>(x, att, ln2_g + i * D_, ln2_b + i * D_, x);
    }

    // head (tiny, fp32)
    sgemm32<true, true><<<dim3(16, 1, 1), 256>>>(
        x + (S_ - 1) * D_, op_w1, op_b1, hh, B_, FF_, D_, S_ * D_, D_, FF_);
    head_out<<<B_, 256>>>(hh, op_w2, op_b2, out);
}